// round 16
// baseline (speedup 1.0000x reference)
#include <cuda_runtime.h>

#define NW 6
#define NL 4
#define HP 112
#define WP 112
#define NB 8
#define OC 16
#define NPIX (NB*HP*WP)

__device__ float g_y[NB*OC*HP*WP];

// ---------------------------------------------------------------------------
// Fused pixels kernel. PROLOGUE kept SMALL in code size (rolled loops) to
// avoid the cold-I$ serial fetch: circuit sim (8 warps, register amplitudes,
// variable-stride shuffles) -> M_w -> 27-term trig table sT. MAIN (fully
// unrolled, throughput part): two adjacent patch pixels per thread.
// ---------------------------------------------------------------------------
__global__ void __launch_bounds__(256)
k_pixels(const float* __restrict__ x,
         const float* __restrict__ w,
         const float* __restrict__ fcw,
         const float* __restrict__ fcb,
         const float* __restrict__ lng,
         const float* __restrict__ lnb)
{
    __shared__ float2 sU[24][4];
    __shared__ float2 phi[8][65];
    __shared__ float  sD[4][64][13];
    __shared__ float  Mre[6][8][8];
    __shared__ float  Mim[6][8][8];
    __shared__ float  sT[162], sFC[96], sFB[16], sG[16], sB[16];

    const int tid  = threadIdx.x;          // 256 threads = 8 warps
    const int wrp  = tid >> 5;
    const int lane = tid & 31;
    const unsigned FULL = 0xFFFFFFFFu;

    if (tid < 96)  sFC[tid] = fcw[tid];
    if (tid >= 96  && tid < 112) sFB[tid - 96]  = fcb[tid - 96];
    if (tid >= 112 && tid < 128) sG [tid - 112] = lng[tid - 112];
    if (tid >= 128 && tid < 144) sB [tid - 128] = lnb[tid - 128];

    if (tid >= 160 && tid < 184) {
        const int gi = tid - 160;
        const float ph = w[gi*3 + 0];
        const float th = w[gi*3 + 1];
        const float om = w[gi*3 + 2];
        const float ch = cosf(0.5f * th), sh = sinf(0.5f * th);
        float cp, sp, cm, sm;
        sincosf(-0.5f * (ph + om), &sp, &cp);
        sincosf(-0.5f * (ph - om), &sm, &cm);
        sU[gi][0] = make_float2( cp*ch,  sp*ch);
        sU[gi][1] = make_float2(-cm*sh,  sm*sh);
        sU[gi][2] = make_float2( cm*sh,  sm*sh);
        sU[gi][3] = make_float2( cp*ch, -sp*ch);
    }
    __syncthreads();

    // ---- circuit (ROLLED: small code footprint) ----
    {
        float ar = (lane == wrp * 8) ? 1.f : 0.f, ai = 0.f;
        float br = (lane + 32 == wrp * 8) ? 1.f : 0.f, bi = 0.f;

        #pragma unroll 1
        for (int l = 0; l < NL; l++) {
            // q = 0: stride-32 butterfly is the (a,b) register pair
            {
                const float2 u00 = sU[l*6][0], u01 = sU[l*6][1];
                const float2 u10 = sU[l*6][2], u11 = sU[l*6][3];
                const float nar = u00.x*ar - u00.y*ai + u01.x*br - u01.y*bi;
                const float nai = u00.x*ai + u00.y*ar + u01.x*bi + u01.y*br;
                const float nbr = u10.x*ar - u10.y*ai + u11.x*br - u11.y*bi;
                const float nbi = u10.x*ai + u10.y*ar + u11.x*bi + u11.y*br;
                ar = nar; ai = nai; br = nbr; bi = nbi;
            }
            // q = 1..5: variable-stride shfl butterflies (rolled)
            #pragma unroll 1
            for (int q = 1; q < NW; q++) {
                const int stride = 32 >> q;            // 16,8,4,2,1
                const float2 u00 = sU[l*6+q][0], u01 = sU[l*6+q][1];
                const float2 u10 = sU[l*6+q][2], u11 = sU[l*6+q][3];
                const float par = __shfl_xor_sync(FULL, ar, stride);
                const float pai = __shfl_xor_sync(FULL, ai, stride);
                const float pbr = __shfl_xor_sync(FULL, br, stride);
                const float pbi = __shfl_xor_sync(FULL, bi, stride);
                const bool hi = (lane & stride) != 0;
                const float2 A  = hi ? u11 : u00;
                const float2 Bc = hi ? u10 : u01;
                {
                    const float nr = A.x*ar - A.y*ai + Bc.x*par - Bc.y*pai;
                    const float ni = A.x*ai + A.y*ar + Bc.x*pai + Bc.y*par;
                    ar = nr; ai = ni;
                }
                {
                    const float nr = A.x*br - A.y*bi + Bc.x*pbr - Bc.y*pbi;
                    const float ni = A.x*bi + A.y*br + Bc.x*pbi + Bc.y*pbr;
                    br = nr; bi = ni;
                }
            }
            // CNOT ring composite permutation (rolled)
            const int r = l % (NW - 1) + 1;
            int i0 = lane, i1 = lane + 32;
            #pragma unroll 1
            for (int q = NW - 1; q >= 0; q--) {
                const int cpos = 5 - q;
                const int tpos = 5 - ((q + r) % NW);
                i0 ^= ((i0 >> cpos) & 1) << tpos;
                i1 ^= ((i1 >> cpos) & 1) << tpos;
            }
            const float g0ar = __shfl_sync(FULL, ar, i0 & 31);
            const float g0ai = __shfl_sync(FULL, ai, i0 & 31);
            const float g0br = __shfl_sync(FULL, br, i0 & 31);
            const float g0bi = __shfl_sync(FULL, bi, i0 & 31);
            const float g1ar = __shfl_sync(FULL, ar, i1 & 31);
            const float g1ai = __shfl_sync(FULL, ai, i1 & 31);
            const float g1br = __shfl_sync(FULL, br, i1 & 31);
            const float g1bi = __shfl_sync(FULL, bi, i1 & 31);
            ar = (i0 < 32) ? g0ar : g0br;
            ai = (i0 < 32) ? g0ai : g0bi;
            br = (i1 < 32) ? g1ar : g1br;
            bi = (i1 < 32) ? g1ai : g1bi;
        }
        phi[wrp][lane]      = make_float2(ar, ai);
        phi[wrp][lane + 32] = make_float2(br, bi);
    }
    __syncthreads();

    // ---- Phase D1 (unroll 4: moderate code size) ----
    {
        const int pair = tid & 63, chunk = tid >> 6;
        const int i = pair >> 3, jj = pair & 7;
        const float s0 = (chunk & 2) ? -1.f : 1.f;
        const float s1 = (chunk & 1) ? -1.f : 1.f;
        float acc[12];
        #pragma unroll
        for (int m = 0; m < 12; m++) acc[m] = 0.f;
        #pragma unroll 4
        for (int k = 0; k < 16; k++) {
            const int t = chunk * 16 + k;
            const float2 a = phi[i][t], bb = phi[jj][t];
            const float pre = a.x*bb.x + a.y*bb.y;
            const float pim = a.x*bb.y - a.y*bb.x;
            acc[0]  += pre;  acc[1]  += pim;
            acc[2]  += pre;  acc[3]  += pim;
            if (k & 8) { acc[4] -= pre; acc[5] -= pim; } else { acc[4] += pre; acc[5] += pim; }
            if (k & 4) { acc[6] -= pre; acc[7] -= pim; } else { acc[6] += pre; acc[7] += pim; }
            if (k & 2) { acc[8] -= pre; acc[9] -= pim; } else { acc[8] += pre; acc[9] += pim; }
            if (k & 1) { acc[10] -= pre; acc[11] -= pim; } else { acc[10] += pre; acc[11] += pim; }
        }
        acc[0] *= s0; acc[1] *= s0;
        acc[2] *= s1; acc[3] *= s1;
        #pragma unroll
        for (int m = 0; m < 12; m++) sD[chunk][pair][m] = acc[m];
    }
    __syncthreads();

    // ---- Phase D2: reduce 4 chunks -> Mre/Mim ----
    for (int o = tid; o < 768; o += 256) {
        const int c = o & 1, pair = (o >> 1) & 63, q = o >> 7;
        const float s = sD[0][pair][2*q+c] + sD[1][pair][2*q+c]
                      + sD[2][pair][2*q+c] + sD[3][pair][2*q+c];
        const int i = pair >> 3, jj = pair & 7;
        if (c) Mim[q][i][jj] = s; else Mre[q][i][jj] = s;
    }
    __syncthreads();

    // ---- Phase E (rolled): 8 contributing (i,jj) pairs per term -> sT ----
    if (tid < 6 * 27) {
        const int q = tid / 27, term = tid % 27;
        const int tt[3] = { term / 9, (term / 3) % 3, term % 3 };
        float acc = 0.f;
        #pragma unroll 1
        for (int k = 0; k < 8; k++) {
            int i = 0, jj = 0;
            float sgn = 0.125f;
            #pragma unroll
            for (int c = 0; c < 3; c++) {
                const int sel = (k >> c) & 1;
                const int t = tt[c];
                int bi, bj;
                if (t == 2) { bi = sel ^ 1; bj = sel; }
                else {
                    bi = sel; bj = sel;
                    if (t == 1 && sel == 1) sgn = -sgn;
                }
                i  |= bi << (2 - c);
                jj |= bj << (2 - c);
            }
            const int kph = (__popc(i) - __popc(jj)) & 3;
            const float mre = Mre[q][i][jj], mim = Mim[q][i][jj];
            const float f = (kph == 0) ? mre : (kph == 1) ? -mim
                          : (kph == 2) ? -mre : mim;
            acc += sgn * f;
        }
        sT[tid] = acc;
    }
    __syncthreads();

    // ============ MAIN (fully unrolled): two patch pixels per thread =======
    const int pp = blockIdx.x * blockDim.x + tid;
    const int WPH = WP / 2;
    const int b   = pp / (HP * WPH);
    const int rem = pp % (HP * WPH);
    const int hp  = rem / WPH, wpp = rem % WPH;

    float g0[3][3], g1[3][3];
    #pragma unroll
    for (int c = 0; c < 3; c++) {
        const float* base = x + (((long)(b * 3 + c) * 224 + 2 * hp) * 224 + 4 * wpp);
        const float4 r0 = *reinterpret_cast<const float4*>(base);
        const float4 r1 = *reinterpret_cast<const float4*>(base + 224);
        const float a0 = 0.25f * (r0.x + r0.y + r1.x + r1.y);
        const float a1 = 0.25f * (r0.z + r0.w + r1.z + r1.w);
        float sn, cs;
        __sincosf(a0, &sn, &cs);
        g0[c][0] = 1.f; g0[c][1] = cs; g0[c][2] = sn;
        __sincosf(a1, &sn, &cs);
        g1[c][0] = 1.f; g1[c][1] = cs; g1[c][2] = sn;
    }

    float2 vout[OC];
    #pragma unroll
    for (int half = 0; half < 2; half++) {
        float (*gg)[3] = half ? g1 : g0;

        float e[6];
        #pragma unroll
        for (int q = 0; q < 6; q++) e[q] = 0.f;
        #pragma unroll
        for (int t0 = 0; t0 < 3; t0++)
            #pragma unroll
            for (int t1 = 0; t1 < 3; t1++) {
                const float p01 = gg[0][t0] * gg[1][t1];
                #pragma unroll
                for (int t2 = 0; t2 < 3; t2++) {
                    const float bas = p01 * gg[2][t2];
                    const int t = (t0 * 3 + t1) * 3 + t2;
                    #pragma unroll
                    for (int q = 0; q < 6; q++) e[q] += sT[q * 27 + t] * bas;
                }
            }

        float y[OC], mu = 0.f;
        #pragma unroll
        for (int o = 0; o < OC; o++) {
            float acc = sFB[o];
            #pragma unroll
            for (int q = 0; q < 6; q++) acc += sFC[o * 6 + q] * e[q];
            y[o] = acc;
            mu += acc;
        }
        mu *= (1.f / OC);
        float var = 0.f;
        #pragma unroll
        for (int o = 0; o < OC; o++) { const float d = y[o] - mu; var += d * d; }
        var *= (1.f / OC);
        const float inv = rsqrtf(var + 1e-5f);
        #pragma unroll
        for (int o = 0; o < OC; o++) {
            const float v = fmaxf((y[o] - mu) * inv * sG[o] + sB[o], 0.f);
            if (half) vout[o].y = v; else vout[o].x = v;
        }
    }

    #pragma unroll
    for (int o = 0; o < OC; o++) {
        *reinterpret_cast<float2*>(
            &g_y[(((long)b * OC + o) * HP + hp) * WP + 2 * wpp]) = vout[o];
    }
}

// ---------------------------------------------------------------------------
// Kernel 2 (R10 version, best measured): 2x bilinear upsample, register
// gather. One thread = 2 output rows x 4 cols: 9 LDG, ~40 FMA, 2 STG.128.
// jax half-pixel weights, clamped edges.
// ---------------------------------------------------------------------------
__global__ void __launch_bounds__(256)
k_resize(float* __restrict__ out)
{
    const int idx = blockIdx.x * 256 + threadIdx.x;   // 3136 blocks exactly
    const int c4 = idx % 56;
    const int m  = (idx / 56) % HP;
    const int pl = idx / (56 * HP);
    const float* yb = g_y + (long)pl * HP * WP;

    const int rm = max(m - 1, 0), rp = min(m + 1, HP - 1);
    const int c0 = 2 * c4;
    const int cm = max(c0 - 1, 0), c2 = min(c0 + 2, WP - 1);

    float hA[3], hB[3], hC[3], hD[3];
    const int rows[3] = { rm, m, rp };
    #pragma unroll
    for (int r = 0; r < 3; r++) {
        const float* rowp = yb + rows[r] * WP;
        const float  vm1 = __ldg(rowp + cm);
        const float2 v01 = *reinterpret_cast<const float2*>(rowp + c0);
        const float  v2  = __ldg(rowp + c2);
        hA[r] = 0.25f * vm1   + 0.75f * v01.x;
        hB[r] = 0.75f * v01.x + 0.25f * v01.y;
        hC[r] = 0.25f * v01.x + 0.75f * v01.y;
        hD[r] = 0.75f * v01.y + 0.25f * v2;
    }

    float* obase = out + (((long)pl * 224 + 2 * m) * 224 + 4 * c4);
    *reinterpret_cast<float4*>(obase) = make_float4(
        0.25f * hA[0] + 0.75f * hA[1],
        0.25f * hB[0] + 0.75f * hB[1],
        0.25f * hC[0] + 0.75f * hC[1],
        0.25f * hD[0] + 0.75f * hD[1]);
    *reinterpret_cast<float4*>(obase + 224) = make_float4(
        0.75f * hA[1] + 0.25f * hA[2],
        0.75f * hB[1] + 0.25f * hB[2],
        0.75f * hC[1] + 0.25f * hC[2],
        0.75f * hD[1] + 0.25f * hD[2]);
}

extern "C" void kernel_launch(void* const* d_in, const int* in_sizes, int n_in,
                              void* d_out, int out_size)
{
    const float* x   = (const float*)d_in[0];
    const float* wts = (const float*)d_in[1];
    const float* fcw = (const float*)d_in[2];
    const float* fcb = (const float*)d_in[3];
    const float* lng = (const float*)d_in[4];
    const float* lnb = (const float*)d_in[5];
    float* out = (float*)d_out;

    k_pixels<<<NPIX / 2 / 256, 256>>>(x, wts, fcw, fcb, lng, lnb);
    k_resize<<<(56 * HP * NB * OC) / 256, 256>>>(out);
}

// round 17
// speedup vs baseline: 1.0935x; 1.0935x over previous
#include <cuda_runtime.h>

#define NW 6
#define NL 4
#define HP 112
#define WP 112
#define NB 8
#define OC 16
#define NPIX (NB*HP*WP)

__device__ float g_y[NB*OC*HP*WP];

// ---------------------------------------------------------------------------
// Fused pixels kernel, SINGLE WAVE: 98 blocks x 512 threads = exactly
// NPIX/2 pixel-pairs, 98 <= 148 SMs so every block's redundant prologue runs
// concurrently (R10 paid it twice: 196 blocks = 2 waves).
// PROLOGUE: circuit sim (warps 0-7) -> Phase D (threads 0-255) -> trig table.
// MAIN: one pixel-pair per thread (fully unrolled).
// ---------------------------------------------------------------------------
__global__ void __launch_bounds__(512)
k_pixels(const float* __restrict__ x,
         const float* __restrict__ w,
         const float* __restrict__ fcw,
         const float* __restrict__ fcb,
         const float* __restrict__ lng,
         const float* __restrict__ lnb)
{
    __shared__ float2 sU[24][4];
    __shared__ float2 phi[8][65];
    __shared__ float  sD[4][64][13];
    __shared__ float  Mre[6][8][8];
    __shared__ float  Mim[6][8][8];
    __shared__ float  sT[162], sFC[96], sFB[16], sG[16], sB[16];

    const int tid  = threadIdx.x;          // 512 threads = 16 warps
    const int wrp  = tid >> 5;
    const int lane = tid & 31;
    const unsigned FULL = 0xFFFFFFFFu;

    if (tid < 96)  sFC[tid] = fcw[tid];
    if (tid >= 96  && tid < 112) sFB[tid - 96]  = fcb[tid - 96];
    if (tid >= 112 && tid < 128) sG [tid - 112] = lng[tid - 112];
    if (tid >= 128 && tid < 144) sB [tid - 128] = lnb[tid - 128];

    if (tid >= 160 && tid < 184) {
        const int gi = tid - 160;
        const float ph = w[gi*3 + 0];
        const float th = w[gi*3 + 1];
        const float om = w[gi*3 + 2];
        const float ch = cosf(0.5f * th), sh = sinf(0.5f * th);
        float cp, sp, cm, sm;
        sincosf(-0.5f * (ph + om), &sp, &cp);
        sincosf(-0.5f * (ph - om), &sm, &cm);
        sU[gi][0] = make_float2( cp*ch,  sp*ch);
        sU[gi][1] = make_float2(-cm*sh,  sm*sh);
        sU[gi][2] = make_float2( cm*sh,  sm*sh);
        sU[gi][3] = make_float2( cp*ch, -sp*ch);
    }
    __syncthreads();

    // ---- circuit: warps 0-7, one basis state each (fully unrolled) ----
    if (wrp < 8) {
        float ar = (lane == wrp * 8) ? 1.f : 0.f, ai = 0.f;
        float br = (lane + 32 == wrp * 8) ? 1.f : 0.f, bi = 0.f;

        for (int l = 0; l < NL; l++) {
            #pragma unroll
            for (int q = 0; q < NW; q++) {
                const float2 u00 = sU[l*6+q][0], u01 = sU[l*6+q][1];
                const float2 u10 = sU[l*6+q][2], u11 = sU[l*6+q][3];
                if (q == 0) {
                    const float nar = u00.x*ar - u00.y*ai + u01.x*br - u01.y*bi;
                    const float nai = u00.x*ai + u00.y*ar + u01.x*bi + u01.y*br;
                    const float nbr = u10.x*ar - u10.y*ai + u11.x*br - u11.y*bi;
                    const float nbi = u10.x*ai + u10.y*ar + u11.x*bi + u11.y*br;
                    ar = nar; ai = nai; br = nbr; bi = nbi;
                } else {
                    const int stride = 1 << (5 - q);
                    const float par = __shfl_xor_sync(FULL, ar, stride);
                    const float pai = __shfl_xor_sync(FULL, ai, stride);
                    const float pbr = __shfl_xor_sync(FULL, br, stride);
                    const float pbi = __shfl_xor_sync(FULL, bi, stride);
                    const bool hi = (lane & stride) != 0;
                    const float2 A  = hi ? u11 : u00;
                    const float2 Bc = hi ? u10 : u01;
                    {
                        const float nr = A.x*ar - A.y*ai + Bc.x*par - Bc.y*pai;
                        const float ni = A.x*ai + A.y*ar + Bc.x*pai + Bc.y*par;
                        ar = nr; ai = ni;
                    }
                    {
                        const float nr = A.x*br - A.y*bi + Bc.x*pbr - Bc.y*pbi;
                        const float ni = A.x*bi + A.y*br + Bc.x*pbi + Bc.y*pbr;
                        br = nr; bi = ni;
                    }
                }
            }
            const int r = l % (NW - 1) + 1;
            int i0 = lane, i1 = lane + 32;
            #pragma unroll
            for (int q = NW - 1; q >= 0; q--) {
                const int cpos = 5 - q;
                const int tpos = 5 - ((q + r) % NW);
                i0 ^= ((i0 >> cpos) & 1) << tpos;
                i1 ^= ((i1 >> cpos) & 1) << tpos;
            }
            const float g0ar = __shfl_sync(FULL, ar, i0 & 31);
            const float g0ai = __shfl_sync(FULL, ai, i0 & 31);
            const float g0br = __shfl_sync(FULL, br, i0 & 31);
            const float g0bi = __shfl_sync(FULL, bi, i0 & 31);
            const float g1ar = __shfl_sync(FULL, ar, i1 & 31);
            const float g1ai = __shfl_sync(FULL, ai, i1 & 31);
            const float g1br = __shfl_sync(FULL, br, i1 & 31);
            const float g1bi = __shfl_sync(FULL, bi, i1 & 31);
            ar = (i0 < 32) ? g0ar : g0br;
            ai = (i0 < 32) ? g0ai : g0bi;
            br = (i1 < 32) ? g1ar : g1br;
            bi = (i1 < 32) ? g1ai : g1bi;
        }
        phi[wrp][lane]      = make_float2(ar, ai);
        phi[wrp][lane + 32] = make_float2(br, bi);
    }
    __syncthreads();

    // ---- Phase D1: threads 0-255 (pair = tid&63 fast, chunk = tid>>6) ----
    if (tid < 256) {
        const int pair = tid & 63, chunk = tid >> 6;
        const int i = pair >> 3, jj = pair & 7;
        const float s0 = (chunk & 2) ? -1.f : 1.f;
        const float s1 = (chunk & 1) ? -1.f : 1.f;
        float acc[12];
        #pragma unroll
        for (int m = 0; m < 12; m++) acc[m] = 0.f;
        #pragma unroll
        for (int k = 0; k < 16; k++) {
            const int t = chunk * 16 + k;
            const float2 a = phi[i][t], bb = phi[jj][t];
            const float pre = a.x*bb.x + a.y*bb.y;
            const float pim = a.x*bb.y - a.y*bb.x;
            acc[0]  += pre;  acc[1]  += pim;
            acc[2]  += pre;  acc[3]  += pim;
            if (k & 8) { acc[4] -= pre; acc[5] -= pim; } else { acc[4] += pre; acc[5] += pim; }
            if (k & 4) { acc[6] -= pre; acc[7] -= pim; } else { acc[6] += pre; acc[7] += pim; }
            if (k & 2) { acc[8] -= pre; acc[9] -= pim; } else { acc[8] += pre; acc[9] += pim; }
            if (k & 1) { acc[10] -= pre; acc[11] -= pim; } else { acc[10] += pre; acc[11] += pim; }
        }
        acc[0] *= s0; acc[1] *= s0;
        acc[2] *= s1; acc[3] *= s1;
        #pragma unroll
        for (int m = 0; m < 12; m++) sD[chunk][pair][m] = acc[m];
    }
    __syncthreads();

    // ---- Phase D2: reduce 4 chunks -> Mre/Mim (768 outputs, 512 thr) ----
    if (tid < 768) {
        for (int o = tid; o < 768; o += 512) {
            const int c = o & 1, pair = (o >> 1) & 63, q = o >> 7;
            const float s = sD[0][pair][2*q+c] + sD[1][pair][2*q+c]
                          + sD[2][pair][2*q+c] + sD[3][pair][2*q+c];
            const int i = pair >> 3, jj = pair & 7;
            if (c) Mim[q][i][jj] = s; else Mre[q][i][jj] = s;
        }
    }
    __syncthreads();

    // ---- Phase E: 8 contributing (i,jj) pairs per term -> sT ----
    if (tid < 6 * 27) {
        const int q = tid / 27, term = tid % 27;
        const int tt[3] = { term / 9, (term / 3) % 3, term % 3 };
        float acc = 0.f;
        #pragma unroll
        for (int k = 0; k < 8; k++) {
            int i = 0, jj = 0;
            float sgn = 0.125f;
            #pragma unroll
            for (int c = 0; c < 3; c++) {
                const int sel = (k >> c) & 1;
                const int t = tt[c];
                int bi, bj;
                if (t == 2) { bi = sel ^ 1; bj = sel; }
                else {
                    bi = sel; bj = sel;
                    if (t == 1 && sel == 1) sgn = -sgn;
                }
                i  |= bi << (2 - c);
                jj |= bj << (2 - c);
            }
            const int kph = (__popc(i) - __popc(jj)) & 3;
            const float mre = Mre[q][i][jj], mim = Mim[q][i][jj];
            const float f = (kph == 0) ? mre : (kph == 1) ? -mim
                          : (kph == 2) ? -mre : mim;
            acc += sgn * f;
        }
        sT[tid] = acc;
    }
    __syncthreads();

    // ================== MAIN: one pixel-pair per thread ====================
    const int pp = blockIdx.x * 512 + tid;          // 98*512 = NPIX/2 exactly
    const int WPH = WP / 2;
    const int b   = pp / (HP * WPH);
    const int rem = pp % (HP * WPH);
    const int hp  = rem / WPH, wpp = rem % WPH;

    float g0[3][3], g1[3][3];
    #pragma unroll
    for (int c = 0; c < 3; c++) {
        const float* base = x + (((long)(b * 3 + c) * 224 + 2 * hp) * 224 + 4 * wpp);
        const float4 r0 = *reinterpret_cast<const float4*>(base);
        const float4 r1 = *reinterpret_cast<const float4*>(base + 224);
        const float a0 = 0.25f * (r0.x + r0.y + r1.x + r1.y);
        const float a1 = 0.25f * (r0.z + r0.w + r1.z + r1.w);
        float sn, cs;
        __sincosf(a0, &sn, &cs);
        g0[c][0] = 1.f; g0[c][1] = cs; g0[c][2] = sn;
        __sincosf(a1, &sn, &cs);
        g1[c][0] = 1.f; g1[c][1] = cs; g1[c][2] = sn;
    }

    float2 vout[OC];
    #pragma unroll
    for (int half = 0; half < 2; half++) {
        float (*gg)[3] = half ? g1 : g0;

        float e[6];
        #pragma unroll
        for (int q = 0; q < 6; q++) e[q] = 0.f;
        #pragma unroll
        for (int t0 = 0; t0 < 3; t0++)
            #pragma unroll
            for (int t1 = 0; t1 < 3; t1++) {
                const float p01 = gg[0][t0] * gg[1][t1];
                #pragma unroll
                for (int t2 = 0; t2 < 3; t2++) {
                    const float bas = p01 * gg[2][t2];
                    const int t = (t0 * 3 + t1) * 3 + t2;
                    #pragma unroll
                    for (int q = 0; q < 6; q++) e[q] += sT[q * 27 + t] * bas;
                }
            }

        float y[OC], mu = 0.f;
        #pragma unroll
        for (int o = 0; o < OC; o++) {
            float acc = sFB[o];
            #pragma unroll
            for (int q = 0; q < 6; q++) acc += sFC[o * 6 + q] * e[q];
            y[o] = acc;
            mu += acc;
        }
        mu *= (1.f / OC);
        float var = 0.f;
        #pragma unroll
        for (int o = 0; o < OC; o++) { const float d = y[o] - mu; var += d * d; }
        var *= (1.f / OC);
        const float inv = rsqrtf(var + 1e-5f);
        #pragma unroll
        for (int o = 0; o < OC; o++) {
            const float v = fmaxf((y[o] - mu) * inv * sG[o] + sB[o], 0.f);
            if (half) vout[o].y = v; else vout[o].x = v;
        }
    }

    #pragma unroll
    for (int o = 0; o < OC; o++) {
        *reinterpret_cast<float2*>(
            &g_y[(((long)b * OC + o) * HP + hp) * WP + 2 * wpp]) = vout[o];
    }
}

// ---------------------------------------------------------------------------
// Kernel 2 (R10 version, best measured): 2x bilinear upsample, register
// gather. One thread = 2 output rows x 4 cols: 9 LDG, ~40 FMA, 2 STG.128.
// ---------------------------------------------------------------------------
__global__ void __launch_bounds__(256)
k_resize(float* __restrict__ out)
{
    const int idx = blockIdx.x * 256 + threadIdx.x;   // 3136 blocks exactly
    const int c4 = idx % 56;
    const int m  = (idx / 56) % HP;
    const int pl = idx / (56 * HP);
    const float* yb = g_y + (long)pl * HP * WP;

    const int rm = max(m - 1, 0), rp = min(m + 1, HP - 1);
    const int c0 = 2 * c4;
    const int cm = max(c0 - 1, 0), c2 = min(c0 + 2, WP - 1);

    float hA[3], hB[3], hC[3], hD[3];
    const int rows[3] = { rm, m, rp };
    #pragma unroll
    for (int r = 0; r < 3; r++) {
        const float* rowp = yb + rows[r] * WP;
        const float  vm1 = __ldg(rowp + cm);
        const float2 v01 = *reinterpret_cast<const float2*>(rowp + c0);
        const float  v2  = __ldg(rowp + c2);
        hA[r] = 0.25f * vm1   + 0.75f * v01.x;
        hB[r] = 0.75f * v01.x + 0.25f * v01.y;
        hC[r] = 0.25f * v01.x + 0.75f * v01.y;
        hD[r] = 0.75f * v01.y + 0.25f * v2;
    }

    float* obase = out + (((long)pl * 224 + 2 * m) * 224 + 4 * c4);
    *reinterpret_cast<float4*>(obase) = make_float4(
        0.25f * hA[0] + 0.75f * hA[1],
        0.25f * hB[0] + 0.75f * hB[1],
        0.25f * hC[0] + 0.75f * hC[1],
        0.25f * hD[0] + 0.75f * hD[1]);
    *reinterpret_cast<float4*>(obase + 224) = make_float4(
        0.75f * hA[1] + 0.25f * hA[2],
        0.75f * hB[1] + 0.25f * hB[2],
        0.75f * hC[1] + 0.25f * hC[2],
        0.75f * hD[1] + 0.25f * hD[2]);
}

extern "C" void kernel_launch(void* const* d_in, const int* in_sizes, int n_in,
                              void* d_out, int out_size)
{
    const float* x   = (const float*)d_in[0];
    const float* wts = (const float*)d_in[1];
    const float* fcw = (const float*)d_in[2];
    const float* fcb = (const float*)d_in[3];
    const float* lng = (const float*)d_in[4];
    const float* lnb = (const float*)d_in[5];
    float* out = (float*)d_out;

    k_pixels<<<98, 512>>>(x, wts, fcw, fcb, lng, lnb);
    k_resize<<<(56 * HP * NB * OC) / 256, 256>>>(out);
}